// round 5
// baseline (speedup 1.0000x reference)
#include <cuda_runtime.h>
#include <math.h>

#define NCAT   1024
#define INDIM  1024
#define HDIM   2048
#define GDIM   (4 * HDIM)      // 8192
#define OUTDIM 32000
#define WOUT_K (NCAT + HDIM)   // 3072

// Scratch (no allocations allowed)
__device__ float g_gates0[GDIM];
__device__ float g_gates1[GDIM];
__device__ float g_h1[HDIM];
__device__ float g_h2[HDIM];
__device__ float g_logits[OUTDIM];
__device__ unsigned int g_cnt0 = 0;
__device__ unsigned int g_cnt1 = 0;
__device__ unsigned int g_cnt2 = 0;

__device__ __forceinline__ float f4dot(float4 a, float4 b) {
    return a.x * b.x + a.y * b.y + a.z * b.z + a.w * b.w;
}
__device__ __forceinline__ float warp_reduce(float acc) {
#pragma unroll
    for (int off = 16; off; off >>= 1)
        acc += __shfl_down_sync(0xffffffffu, acc, off);
    return acc;
}
__device__ __forceinline__ float fast_sigmoid(float x) {
    return 1.0f / (1.0f + __expf(-x));
}
__device__ __forceinline__ float fast_tanh(float x) {
    // tanh(x) = 1 - 2/(e^{2x}+1)
    return 1.0f - 2.0f / (__expf(2.0f * x) + 1.0f);
}

// Returns true for the whole block if this block is the last of `total` to arrive.
__device__ __forceinline__ bool last_block(unsigned int* cnt, unsigned int total) {
    __shared__ bool is_last;
    __syncthreads();
    if (threadIdx.x == 0) {
        __threadfence();
        unsigned int v = atomicAdd(cnt, 1u);
        is_last = (v == total - 1u);
        if (is_last) *cnt = 0u;  // reset for next graph replay
    }
    __syncthreads();
    return is_last;
}

// ---------------------------------------------------------------------------
// K1: all input-only matvecs fused; last gates0-block also runs cell0.
//   blocks [0, 1024):    gates0 rows (8 warps/block)
//   blocks [1024, 2048): gates1 partial rows
//   blocks [2048, 6048): logits-cat rows
__global__ void __launch_bounds__(256) k1_input_matvecs(
    const float* __restrict__ cat, const float* __restrict__ inp,
    const float* __restrict__ hidden, const float* __restrict__ cell,
    const float* __restrict__ w_ih_l0, const float* __restrict__ w_hh_l0,
    const float* __restrict__ b_ih_l0, const float* __restrict__ b_hh_l0,
    const float* __restrict__ w_hh_l1,
    const float* __restrict__ b_ih_l1, const float* __restrict__ b_hh_l1,
    const float* __restrict__ w_out, const float* __restrict__ b_out,
    float* __restrict__ out_h1, float* __restrict__ out_c1)
{
    int warp = (blockIdx.x * blockDim.x + threadIdx.x) >> 5;
    int lane = threadIdx.x & 31;

    if (warp < GDIM) {
        int r = warp;
        const float4* w1 = (const float4*)(w_ih_l0 + (size_t)r * 2048);
        const float4* w2 = (const float4*)(w_hh_l0 + (size_t)r * 2048);
        const float4* vc = (const float4*)cat;
        const float4* vi = (const float4*)inp;
        const float4* vh = (const float4*)hidden;
        float acc = 0.f;
#pragma unroll
        for (int i = 0; i < 8; i++)
            acc += f4dot(__ldcs(&w1[lane + 32 * i]), vc[lane + 32 * i]);
#pragma unroll
        for (int i = 0; i < 8; i++)
            acc += f4dot(__ldcs(&w1[256 + lane + 32 * i]), vi[lane + 32 * i]);
#pragma unroll
        for (int i = 0; i < 16; i++)
            acc += f4dot(__ldcs(&w2[lane + 32 * i]), vh[lane + 32 * i]);
        acc = warp_reduce(acc);
        if (lane == 0) g_gates0[r] = acc + b_ih_l0[r] + b_hh_l0[r];

        // blocks 0..1023 own all of gates0; last one runs cell0 (overlaps
        // with the still-running logits-cat blocks).
        if (last_block(&g_cnt0, GDIM / 8)) {
            for (int j = threadIdx.x; j < HDIM; j += blockDim.x) {
                float ig = fast_sigmoid(g_gates0[j]);
                float fg = fast_sigmoid(g_gates0[HDIM + j]);
                float gg = fast_tanh(g_gates0[2 * HDIM + j]);
                float og = fast_sigmoid(g_gates0[3 * HDIM + j]);
                float c_new = fg * cell[j] + ig * gg;
                float h_new = og * fast_tanh(c_new);
                g_h1[j] = h_new;
                out_h1[j] = h_new;
                out_c1[j] = c_new;
            }
        }
    } else if (warp < 2 * GDIM) {
        int r = warp - GDIM;
        const float4* w  = (const float4*)(w_hh_l1 + (size_t)r * 2048);
        const float4* vh = (const float4*)(hidden + HDIM);
        float acc = 0.f;
#pragma unroll
        for (int i = 0; i < 16; i++)
            acc += f4dot(__ldcs(&w[lane + 32 * i]), vh[lane + 32 * i]);
        acc = warp_reduce(acc);
        if (lane == 0) g_gates1[r] = acc + b_ih_l1[r] + b_hh_l1[r];
    } else {
        int r = warp - 2 * GDIM;
        if (r < OUTDIM) {
            const float4* w  = (const float4*)(w_out + (size_t)r * WOUT_K);
            const float4* vc = (const float4*)cat;
            float acc = 0.f;
#pragma unroll
            for (int i = 0; i < 8; i++)
                acc += f4dot(__ldcs(&w[lane + 32 * i]), vc[lane + 32 * i]);
            acc = warp_reduce(acc);
            if (lane == 0) g_logits[r] = acc + b_out[r];
        }
    }
}

// ---------------------------------------------------------------------------
// K2: g_gates1[r] += w_ih_l1[r] @ h1; last block runs cell1.
__global__ void __launch_bounds__(256) k2_l1_ih(
    const float* __restrict__ w_ih_l1, const float* __restrict__ cell,
    float* __restrict__ out_h2, float* __restrict__ out_c2)
{
    int warp = (blockIdx.x * blockDim.x + threadIdx.x) >> 5;
    int lane = threadIdx.x & 31;
    {
        const float4* w  = (const float4*)(w_ih_l1 + (size_t)warp * 2048);
        const float4* vh = (const float4*)g_h1;
        float acc = 0.f;
#pragma unroll
        for (int i = 0; i < 16; i++)
            acc += f4dot(__ldcs(&w[lane + 32 * i]), vh[lane + 32 * i]);
        acc = warp_reduce(acc);
        if (lane == 0) g_gates1[warp] += acc;
    }
    if (last_block(&g_cnt1, GDIM / 8)) {
        for (int j = threadIdx.x; j < HDIM; j += blockDim.x) {
            float ig = fast_sigmoid(g_gates1[j]);
            float fg = fast_sigmoid(g_gates1[HDIM + j]);
            float gg = fast_tanh(g_gates1[2 * HDIM + j]);
            float og = fast_sigmoid(g_gates1[3 * HDIM + j]);
            float c_new = fg * cell[HDIM + j] + ig * gg;
            float h_new = og * fast_tanh(c_new);
            g_h2[j] = h_new;
            out_h2[j] = h_new;
            out_c2[j] = c_new;
        }
    }
}

// ---------------------------------------------------------------------------
// K3: g_logits[r] += w_out[r, 1024:3072] @ h2; last block runs log_softmax.
__global__ void __launch_bounds__(256) k3_out_h(
    const float* __restrict__ w_out, float* __restrict__ out_logp)
{
    int warp = (blockIdx.x * blockDim.x + threadIdx.x) >> 5;
    int lane = threadIdx.x & 31;
    {
        const float4* w  = (const float4*)(w_out + (size_t)warp * WOUT_K + NCAT);
        const float4* vh = (const float4*)g_h2;
        float acc = 0.f;
#pragma unroll
        for (int i = 0; i < 16; i++)
            acc += f4dot(__ldcs(&w[lane + 32 * i]), vh[lane + 32 * i]);
        acc = warp_reduce(acc);
        if (lane == 0) g_logits[warp] += acc;
    }
    if (last_block(&g_cnt2, OUTDIM / 8)) {
        __shared__ float red[8];
        int tid = threadIdx.x;
        int l = tid & 31, wd = tid >> 5;

        float m = -INFINITY;
        for (int i = tid; i < OUTDIM; i += 256) m = fmaxf(m, g_logits[i]);
#pragma unroll
        for (int off = 16; off; off >>= 1)
            m = fmaxf(m, __shfl_xor_sync(0xffffffffu, m, off));
        if (l == 0) red[wd] = m;
        __syncthreads();
        if (wd == 0) {
            float v = (l < 8) ? red[l] : -INFINITY;
#pragma unroll
            for (int off = 4; off; off >>= 1)
                v = fmaxf(v, __shfl_xor_sync(0xffffffffu, v, off));
            if (l == 0) red[0] = v;
        }
        __syncthreads();
        m = red[0];
        __syncthreads();

        float s = 0.f;
        for (int i = tid; i < OUTDIM; i += 256) s += __expf(g_logits[i] - m);
#pragma unroll
        for (int off = 16; off; off >>= 1)
            s += __shfl_xor_sync(0xffffffffu, s, off);
        if (l == 0) red[wd] = s;
        __syncthreads();
        if (wd == 0) {
            float v = (l < 8) ? red[l] : 0.f;
#pragma unroll
            for (int off = 4; off; off >>= 1)
                v += __shfl_xor_sync(0xffffffffu, v, off);
            if (l == 0) red[0] = v;
        }
        __syncthreads();
        float lse = m + __logf(red[0]);

        for (int i = tid; i < OUTDIM; i += 256)
            out_logp[i] = g_logits[i] - lse;
    }
}

// ---------------------------------------------------------------------------
extern "C" void kernel_launch(void* const* d_in, const int* in_sizes, int n_in,
                              void* d_out, int out_size) {
    const float* category = (const float*)d_in[0];
    const float* input    = (const float*)d_in[1];
    const float* hidden   = (const float*)d_in[2];
    const float* cell     = (const float*)d_in[3];
    const float* w_ih_l0  = (const float*)d_in[4];
    const float* w_hh_l0  = (const float*)d_in[5];
    const float* b_ih_l0  = (const float*)d_in[6];
    const float* b_hh_l0  = (const float*)d_in[7];
    const float* w_ih_l1  = (const float*)d_in[8];
    const float* w_hh_l1  = (const float*)d_in[9];
    const float* b_ih_l1  = (const float*)d_in[10];
    const float* b_hh_l1  = (const float*)d_in[11];
    const float* w_out    = (const float*)d_in[12];
    const float* b_out    = (const float*)d_in[13];

    float* out = (float*)d_out;
    float* out_logp = out;
    float* out_h1 = out + OUTDIM;
    float* out_h2 = out + OUTDIM + HDIM;
    float* out_c1 = out + OUTDIM + 2 * HDIM;
    float* out_c2 = out + OUTDIM + 3 * HDIM;

    // K1: 6048 blocks = 1024 gates0 + 1024 gates1-partial + 4000 logits-cat
    k1_input_matvecs<<<6048, 256>>>(
        category, input, hidden, cell,
        w_ih_l0, w_hh_l0, b_ih_l0, b_hh_l0,
        w_hh_l1, b_ih_l1, b_hh_l1,
        w_out, b_out, out_h1, out_c1);

    // K2: 1024 blocks, 8 warps/block, one row/warp; last block runs cell1.
    k2_l1_ih<<<GDIM / 8, 256>>>(w_ih_l1, cell, out_h2, out_c2);

    // K3: 4000 blocks; last block runs log_softmax.
    k3_out_h<<<OUTDIM / 8, 256>>>(w_out, out_logp);
}

// round 6
// speedup vs baseline: 1.2139x; 1.2139x over previous
#include <cuda_runtime.h>
#include <math.h>

#define NCAT   1024
#define INDIM  1024
#define HDIM   2048
#define GDIM   (4 * HDIM)      // 8192
#define OUTDIM 32000
#define WOUT_K (NCAT + HDIM)   // 3072

// Scratch (no allocations allowed)
__device__ float g_gates0[GDIM];
__device__ float g_gates1[GDIM];
__device__ float g_h1[HDIM];
__device__ float g_h2[HDIM];
__device__ float g_logits[OUTDIM];
__device__ unsigned int g_cnt0 = 0;

__device__ __forceinline__ float f4dot(float4 a, float4 b) {
    return a.x * b.x + a.y * b.y + a.z * b.z + a.w * b.w;
}
__device__ __forceinline__ float warp_reduce(float acc) {
#pragma unroll
    for (int off = 16; off; off >>= 1)
        acc += __shfl_down_sync(0xffffffffu, acc, off);
    return acc;
}
__device__ __forceinline__ float fast_sigmoid(float x) {
    return 1.0f / (1.0f + __expf(-x));
}
__device__ __forceinline__ float fast_tanh(float x) {
    return 1.0f - 2.0f / (__expf(2.0f * x) + 1.0f);
}

// ---------------------------------------------------------------------------
// K1: all input-only matvecs, 2 rows per warp.
//   blocks [0, 512):     gates0 rows (16 rows/block); last one also runs cell0
//   blocks [512, 1024):  gates1 partial rows
//   blocks [1024, 3024): logits-cat rows
__global__ void __launch_bounds__(256, 4) k1_input_matvecs(
    const float* __restrict__ cat, const float* __restrict__ inp,
    const float* __restrict__ hidden, const float* __restrict__ cell,
    const float* __restrict__ w_ih_l0, const float* __restrict__ w_hh_l0,
    const float* __restrict__ b_ih_l0, const float* __restrict__ b_hh_l0,
    const float* __restrict__ w_hh_l1,
    const float* __restrict__ b_ih_l1, const float* __restrict__ b_hh_l1,
    const float* __restrict__ w_out, const float* __restrict__ b_out,
    float* __restrict__ out_h1, float* __restrict__ out_c1)
{
    int W = (blockIdx.x * blockDim.x + threadIdx.x) >> 5;  // global warp id
    int lane = threadIdx.x & 31;

    if (W < GDIM / 2) {
        int r0 = 2 * W, r1 = r0 + 1;
        const float4* a0 = (const float4*)(w_ih_l0 + (size_t)r0 * 2048);
        const float4* a1 = (const float4*)(w_ih_l0 + (size_t)r1 * 2048);
        const float4* h0 = (const float4*)(w_hh_l0 + (size_t)r0 * 2048);
        const float4* h1 = (const float4*)(w_hh_l0 + (size_t)r1 * 2048);
        const float4* vc = (const float4*)cat;
        const float4* vi = (const float4*)inp;
        const float4* vh = (const float4*)hidden;
        float acc0 = 0.f, acc1 = 0.f;
#pragma unroll
        for (int i = 0; i < 8; i++) {
            float4 x = vc[lane + 32 * i];
            acc0 += f4dot(__ldcs(&a0[lane + 32 * i]), x);
            acc1 += f4dot(__ldcs(&a1[lane + 32 * i]), x);
        }
#pragma unroll
        for (int i = 0; i < 8; i++) {
            float4 x = vi[lane + 32 * i];
            acc0 += f4dot(__ldcs(&a0[256 + lane + 32 * i]), x);
            acc1 += f4dot(__ldcs(&a1[256 + lane + 32 * i]), x);
        }
#pragma unroll
        for (int i = 0; i < 16; i++) {
            float4 x = vh[lane + 32 * i];
            acc0 += f4dot(__ldcs(&h0[lane + 32 * i]), x);
            acc1 += f4dot(__ldcs(&h1[lane + 32 * i]), x);
        }
        acc0 = warp_reduce(acc0);
        acc1 = warp_reduce(acc1);
        if (lane == 0) g_gates0[r0] = acc0 + b_ih_l0[r0] + b_hh_l0[r0];
        if (lane == 0) g_gates0[r1] = acc1 + b_ih_l0[r1] + b_hh_l0[r1];

        // cell0 in the last gates0 block — overlaps with logits-cat blocks.
        __shared__ bool is_last;
        __syncthreads();
        if (threadIdx.x == 0) {
            __threadfence();
            unsigned int v = atomicAdd(&g_cnt0, 1u);
            is_last = (v == (GDIM / 16) - 1u);
            if (is_last) g_cnt0 = 0u;
        }
        __syncthreads();
        if (is_last) {
            for (int j = threadIdx.x; j < HDIM; j += blockDim.x) {
                float ig = fast_sigmoid(g_gates0[j]);
                float fg = fast_sigmoid(g_gates0[HDIM + j]);
                float gg = fast_tanh(g_gates0[2 * HDIM + j]);
                float og = fast_sigmoid(g_gates0[3 * HDIM + j]);
                float c_new = fg * cell[j] + ig * gg;
                float h_new = og * fast_tanh(c_new);
                g_h1[j] = h_new;
                out_h1[j] = h_new;
                out_c1[j] = c_new;
            }
        }
    } else if (W < GDIM) {
        int r0 = 2 * (W - GDIM / 2), r1 = r0 + 1;
        const float4* w0 = (const float4*)(w_hh_l1 + (size_t)r0 * 2048);
        const float4* w1 = (const float4*)(w_hh_l1 + (size_t)r1 * 2048);
        const float4* vh = (const float4*)(hidden + HDIM);
        float acc0 = 0.f, acc1 = 0.f;
#pragma unroll
        for (int i = 0; i < 16; i++) {
            float4 x = vh[lane + 32 * i];
            acc0 += f4dot(__ldcs(&w0[lane + 32 * i]), x);
            acc1 += f4dot(__ldcs(&w1[lane + 32 * i]), x);
        }
        acc0 = warp_reduce(acc0);
        acc1 = warp_reduce(acc1);
        if (lane == 0) g_gates1[r0] = acc0 + b_ih_l1[r0] + b_hh_l1[r0];
        if (lane == 0) g_gates1[r1] = acc1 + b_ih_l1[r1] + b_hh_l1[r1];
    } else {
        int r0 = 2 * (W - GDIM);
        if (r0 < OUTDIM) {
            int r1 = r0 + 1;
            const float4* w0 = (const float4*)(w_out + (size_t)r0 * WOUT_K);
            const float4* w1 = (const float4*)(w_out + (size_t)r1 * WOUT_K);
            const float4* vc = (const float4*)cat;
            float acc0 = 0.f, acc1 = 0.f;
#pragma unroll
            for (int i = 0; i < 8; i++) {
                float4 x = vc[lane + 32 * i];
                acc0 += f4dot(__ldcs(&w0[lane + 32 * i]), x);
                acc1 += f4dot(__ldcs(&w1[lane + 32 * i]), x);
            }
            acc0 = warp_reduce(acc0);
            acc1 = warp_reduce(acc1);
            if (lane == 0) g_logits[r0] = acc0 + b_out[r0];
            if (lane == 0) g_logits[r1] = acc1 + b_out[r1];
        }
    }
}

// ---------------------------------------------------------------------------
// K2: g_gates1 += w_ih_l1 @ h1, 2 rows/warp.
__global__ void __launch_bounds__(256, 4) k2_l1_ih(const float* __restrict__ w_ih_l1)
{
    int W = (blockIdx.x * blockDim.x + threadIdx.x) >> 5;
    int lane = threadIdx.x & 31;
    int r0 = 2 * W, r1 = r0 + 1;
    const float4* w0 = (const float4*)(w_ih_l1 + (size_t)r0 * 2048);
    const float4* w1 = (const float4*)(w_ih_l1 + (size_t)r1 * 2048);
    const float4* vh = (const float4*)g_h1;
    float acc0 = 0.f, acc1 = 0.f;
#pragma unroll
    for (int i = 0; i < 16; i++) {
        float4 x = vh[lane + 32 * i];
        acc0 += f4dot(__ldcs(&w0[lane + 32 * i]), x);
        acc1 += f4dot(__ldcs(&w1[lane + 32 * i]), x);
    }
    acc0 = warp_reduce(acc0);
    acc1 = warp_reduce(acc1);
    if (lane == 0) g_gates1[r0] += acc0;
    if (lane == 0) g_gates1[r1] += acc1;
}

// ---------------------------------------------------------------------------
// cell1 (separate tiny kernel — no serial tail inside a big stream kernel)
__global__ void lstm_cell1_kernel(const float* __restrict__ cell,
                                  float* __restrict__ out_h2,
                                  float* __restrict__ out_c2) {
    int j = blockIdx.x * blockDim.x + threadIdx.x;
    if (j >= HDIM) return;
    float ig = fast_sigmoid(g_gates1[j]);
    float fg = fast_sigmoid(g_gates1[HDIM + j]);
    float gg = fast_tanh(g_gates1[2 * HDIM + j]);
    float og = fast_sigmoid(g_gates1[3 * HDIM + j]);
    float c_new = fg * cell[HDIM + j] + ig * gg;
    float h_new = og * fast_tanh(c_new);
    g_h2[j] = h_new;
    out_h2[j] = h_new;
    out_c2[j] = c_new;
}

// ---------------------------------------------------------------------------
// K3: g_logits += w_out[:, 1024:3072] @ h2, 2 rows/warp.
__global__ void __launch_bounds__(256, 4) k3_out_h(const float* __restrict__ w_out)
{
    int W = (blockIdx.x * blockDim.x + threadIdx.x) >> 5;
    int lane = threadIdx.x & 31;
    int r0 = 2 * W;
    if (r0 >= OUTDIM) return;
    int r1 = r0 + 1;
    const float4* w0 = (const float4*)(w_out + (size_t)r0 * WOUT_K + NCAT);
    const float4* w1 = (const float4*)(w_out + (size_t)r1 * WOUT_K + NCAT);
    const float4* vh = (const float4*)g_h2;
    float acc0 = 0.f, acc1 = 0.f;
#pragma unroll
    for (int i = 0; i < 16; i++) {
        float4 x = vh[lane + 32 * i];
        acc0 += f4dot(__ldcs(&w0[lane + 32 * i]), x);
        acc1 += f4dot(__ldcs(&w1[lane + 32 * i]), x);
    }
    acc0 = warp_reduce(acc0);
    acc1 = warp_reduce(acc1);
    if (lane == 0) g_logits[r0] += acc0;
    if (lane == 0) g_logits[r1] += acc1;
}

// ---------------------------------------------------------------------------
// log_softmax, one 1024-thread block.
__global__ void log_softmax_kernel(float* __restrict__ out) {
    __shared__ float red[32];
    int tid = threadIdx.x;
    int lane = tid & 31;
    int wid = tid >> 5;

    float m = -INFINITY;
    for (int i = tid; i < OUTDIM; i += 1024) m = fmaxf(m, g_logits[i]);
#pragma unroll
    for (int off = 16; off; off >>= 1)
        m = fmaxf(m, __shfl_xor_sync(0xffffffffu, m, off));
    if (lane == 0) red[wid] = m;
    __syncthreads();
    if (wid == 0) {
        float v = red[lane];
#pragma unroll
        for (int off = 16; off; off >>= 1)
            v = fmaxf(v, __shfl_xor_sync(0xffffffffu, v, off));
        if (lane == 0) red[0] = v;
    }
    __syncthreads();
    m = red[0];
    __syncthreads();

    float s = 0.f;
    for (int i = tid; i < OUTDIM; i += 1024) s += __expf(g_logits[i] - m);
#pragma unroll
    for (int off = 16; off; off >>= 1)
        s += __shfl_xor_sync(0xffffffffu, s, off);
    if (lane == 0) red[wid] = s;
    __syncthreads();
    if (wid == 0) {
        float v = red[lane];
#pragma unroll
        for (int off = 16; off; off >>= 1)
            v += __shfl_xor_sync(0xffffffffu, v, off);
        if (lane == 0) red[0] = v;
    }
    __syncthreads();
    float lse = m + __logf(red[0]);

    for (int i = tid; i < OUTDIM; i += 1024)
        out[i] = g_logits[i] - lse;
}

// ---------------------------------------------------------------------------
extern "C" void kernel_launch(void* const* d_in, const int* in_sizes, int n_in,
                              void* d_out, int out_size) {
    const float* category = (const float*)d_in[0];
    const float* input    = (const float*)d_in[1];
    const float* hidden   = (const float*)d_in[2];
    const float* cell     = (const float*)d_in[3];
    const float* w_ih_l0  = (const float*)d_in[4];
    const float* w_hh_l0  = (const float*)d_in[5];
    const float* b_ih_l0  = (const float*)d_in[6];
    const float* b_hh_l0  = (const float*)d_in[7];
    const float* w_ih_l1  = (const float*)d_in[8];
    const float* w_hh_l1  = (const float*)d_in[9];
    const float* b_ih_l1  = (const float*)d_in[10];
    const float* b_hh_l1  = (const float*)d_in[11];
    const float* w_out    = (const float*)d_in[12];
    const float* b_out    = (const float*)d_in[13];

    float* out = (float*)d_out;
    float* out_logp = out;
    float* out_h1 = out + OUTDIM;
    float* out_h2 = out + OUTDIM + HDIM;
    float* out_c1 = out + OUTDIM + 2 * HDIM;
    float* out_c2 = out + OUTDIM + 3 * HDIM;

    // K1: 3024 blocks = 512 gates0 + 512 gates1-partial + 2000 logits-cat
    k1_input_matvecs<<<3024, 256>>>(
        category, input, hidden, cell,
        w_ih_l0, w_hh_l0, b_ih_l0, b_hh_l0,
        w_hh_l1, b_ih_l1, b_hh_l1,
        w_out, b_out, out_h1, out_c1);

    // K2: 8192 rows, 2 rows/warp, 8 warps/block -> 512 blocks
    k2_l1_ih<<<GDIM / 16, 256>>>(w_ih_l1);

    // cell1
    lstm_cell1_kernel<<<HDIM / 256, 256>>>(cell, out_h2, out_c2);

    // K3: 32000 rows, 2 rows/warp -> 2000 blocks
    k3_out_h<<<OUTDIM / 16, 256>>>(w_out);

    // log_softmax
    log_softmax_kernel<<<1, 1024>>>(out_logp);
}